// round 6
// baseline (speedup 1.0000x reference)
#include <cuda_runtime.h>
#include <cstdint>

// out[b,t,f] = relu( r2[t<16][f] + sum_c sign(x[b,t,c])*sign(w_sc[c,f]) )
//
// conv2's input is ste_sign(relu(...)) == +1 everywhere (sign(0)=+1), so the
// conv1 branch is dead and conv2+bn2 collapse to a per-f constant table (two
// variants: t<16 sees the causal zero-pad on the dilated tap). The shortcut is
// an exact +-1 binary GEMM via XOR+popcount.
//
// R6: (a) single fused precompute kernel (1 block x 1024 thr, coalesced,
// one syncthreads) replacing the 2-kernel chain; (b) main kernel uses a
// warp-private 3-stage cp.async pipeline with ZERO __syncthreads: each thread
// async-copies exactly the 16B quads it alone reads back, so wait_group gives
// full visibility without any barrier.

#define EPSBN 1e-3f
#define NSTAGE 3
#define SROWS 4                       // rows per stage per warp
#define WARP_ROWS 32                  // rows per warp
#define SITER (WARP_ROWS / SROWS)     // 8 stage-iterations
#define ROWS_PER_BLOCK (8 * WARP_ROWS)  // 256
#define TOTAL_ROWS (32 * 8192)          // 262144

__device__ uint4 g_wbits[128];   // f -> packed sign bits (word k bit l <-> channel 4l+k)
__device__ float g_r2[2][128];   // [0]=t>=16 bias table, [1]=t<16 table

// ---------------- fused precompute: one block, 1024 threads ----------------
__global__ void precompute_fused(const float* __restrict__ w2,
                                 const float* __restrict__ w_sc,
                                 const float* __restrict__ beta2,
                                 const float* __restrict__ mean2,
                                 const float* __restrict__ var2) {
    __shared__ int sh01[8][128];
    __shared__ int sh1[8][128];

    int tid = threadIdx.x;
    int f = tid & 127;
    int j = tid >> 7;            // 0..7

    // partial conv2 sign-sums over 16 channels (coalesced across f)
    int S01 = 0, S1 = 0;
#pragma unroll
    for (int cc = 0; cc < 16; ++cc) {
        int c = 16 * j + cc;
        float a  = w2[c * 128 + f];           // tap k=0
        float bb = w2[16384 + c * 128 + f];   // tap k=1
        S01 += ((a >= 0.f) ? 1 : -1) + ((bb >= 0.f) ? 1 : -1);
        S1  += ((bb >= 0.f) ? 1 : -1);
    }
    sh01[j][f] = S01;
    sh1[j][f]  = S1;

    // groups j<4 also pack word j of the shortcut weight sign bits
    // (float4-ballot channel order: word k, bit l <-> channel 4l+k)
    if (j < 4) {
        unsigned w = 0u;
#pragma unroll
        for (int l = 0; l < 32; ++l) {
            if (w_sc[(4 * l + j) * 128 + f] >= 0.f) w |= (1u << l);
        }
        reinterpret_cast<unsigned*>(&g_wbits[f])[j] = w;
    }
    __syncthreads();

    if (tid < 128) {
        int t01 = 0, t1 = 0;
#pragma unroll
        for (int k = 0; k < 8; ++k) { t01 += sh01[k][f]; t1 += sh1[k][f]; }
        float inv = rsqrtf(var2[f] + EPSBN);
        g_r2[0][f] = fmaxf(((float)t01 - mean2[f]) * inv + beta2[f], 0.f);
        g_r2[1][f] = fmaxf(((float)t1  - mean2[f]) * inv + beta2[f], 0.f);
    }
}

// ---------------- cp.async helpers ----------------
__device__ __forceinline__ void cp_async16(uint32_t smem_addr, const void* gptr) {
    asm volatile("cp.async.cg.shared.global [%0], [%1], 16;\n"
                 :: "r"(smem_addr), "l"(gptr));
}
__device__ __forceinline__ void cp_commit() {
    asm volatile("cp.async.commit_group;\n" ::: "memory");
}
template <int N>
__device__ __forceinline__ void cp_wait() {
    asm volatile("cp.async.wait_group %0;\n" :: "n"(N) : "memory");
}

// ---------------- main kernel: warp-private pipeline, no barriers ----------------
__global__ void __launch_bounds__(256, 4)
resblock_main(const float* __restrict__ x, float* __restrict__ out) {
    // [warp][stage][row][lane] float4 : 8*3*4*32*16 = 48 KB
    __shared__ float4 s_x[8][NSTAGE][SROWS * 32];

    int tid  = threadIdx.x;
    int lane = tid & 31;
    int warp = tid >> 5;

    // Hoist this thread's 4 output columns: weights + folded bias (bias + 128)
    uint4 wb0 = g_wbits[4 * lane + 0];
    uint4 wb1 = g_wbits[4 * lane + 1];
    uint4 wb2 = g_wbits[4 * lane + 2];
    uint4 wb3 = g_wbits[4 * lane + 3];
    float bP0 = g_r2[0][4 * lane + 0] + 128.f;
    float bP1 = g_r2[0][4 * lane + 1] + 128.f;
    float bP2 = g_r2[0][4 * lane + 2] + 128.f;
    float bP3 = g_r2[0][4 * lane + 3] + 128.f;

    size_t warp_row0 = (size_t)blockIdx.x * ROWS_PER_BLOCK + (size_t)warp * WARP_ROWS;
    const float4* __restrict__ gx = (const float4*)x + warp_row0 * 32 + lane;
    float4* __restrict__ o4 = (float4*)out;

    uint32_t sbase = (uint32_t)__cvta_generic_to_shared(&s_x[warp][0][0]);

    // prologue: issue stages 0 and 1 (each thread copies ONLY what it reads back)
#pragma unroll
    for (int s = 0; s < 2; ++s) {
#pragma unroll
        for (int r = 0; r < SROWS; ++r) {
            cp_async16(sbase + (uint32_t)((s * SROWS + r) * 32 + lane) * 16,
                       gx + (size_t)(s * SROWS + r) * 32);
        }
        cp_commit();
    }

#pragma unroll
    for (int s = 0; s < SITER; ++s) {
        if (s + 2 < SITER) {
            int ps = s + 2, b = ps % NSTAGE;
#pragma unroll
            for (int r = 0; r < SROWS; ++r) {
                cp_async16(sbase + (uint32_t)((b * SROWS + r) * 32 + lane) * 16,
                           gx + (size_t)(ps * SROWS + r) * 32);
            }
            cp_commit();
            cp_wait<2>();
        } else if (s == SITER - 2) {
            cp_wait<1>();
        } else {
            cp_wait<0>();
        }

        const float4* buf = s_x[warp][s % NSTAGE];
#pragma unroll
        for (int r = 0; r < SROWS; ++r) {
            float4 v = buf[r * 32 + lane];   // this thread's own cp.async result

            unsigned m0 = __ballot_sync(0xffffffffu, v.x >= 0.f);
            unsigned m1 = __ballot_sync(0xffffffffu, v.y >= 0.f);
            unsigned m2 = __ballot_sync(0xffffffffu, v.z >= 0.f);
            unsigned m3 = __ballot_sync(0xffffffffu, v.w >= 0.f);

            size_t row = warp_row0 + (size_t)(s * SROWS + r);

            float p0 = bP0, p1 = bP1, p2 = bP2, p3 = bP3;
            if ((row & 8191) < 16) {               // 512 of 262144 rows
                p0 = g_r2[1][4 * lane + 0] + 128.f;
                p1 = g_r2[1][4 * lane + 1] + 128.f;
                p2 = g_r2[1][4 * lane + 2] + 128.f;
                p3 = g_r2[1][4 * lane + 3] + 128.f;
            }

            int c0 = __popc(m0 ^ wb0.x) + __popc(m1 ^ wb0.y) + __popc(m2 ^ wb0.z) + __popc(m3 ^ wb0.w);
            int c1 = __popc(m0 ^ wb1.x) + __popc(m1 ^ wb1.y) + __popc(m2 ^ wb1.z) + __popc(m3 ^ wb1.w);
            int c2 = __popc(m0 ^ wb2.x) + __popc(m1 ^ wb2.y) + __popc(m2 ^ wb2.z) + __popc(m3 ^ wb2.w);
            int c3 = __popc(m0 ^ wb3.x) + __popc(m1 ^ wb3.y) + __popc(m2 ^ wb3.z) + __popc(m3 ^ wb3.w);

            float4 o;
            o.x = fmaxf(fmaf(-2.f, (float)c0, p0), 0.f);
            o.y = fmaxf(fmaf(-2.f, (float)c1, p1), 0.f);
            o.z = fmaxf(fmaf(-2.f, (float)c2, p2), 0.f);
            o.w = fmaxf(fmaf(-2.f, (float)c3, p3), 0.f);
            o4[row * 32 + lane] = o;
        }
    }
}

extern "C" void kernel_launch(void* const* d_in, const int* in_sizes, int n_in,
                              void* d_out, int out_size) {
    const float* x     = (const float*)d_in[0];
    // d_in[1] = w1 (dead), d_in[4..6] = bn1 params (dead)
    const float* w2    = (const float*)d_in[2];
    const float* w_sc  = (const float*)d_in[3];
    const float* beta2 = (const float*)d_in[7];
    const float* mean2 = (const float*)d_in[8];
    const float* var2  = (const float*)d_in[9];
    float* out = (float*)d_out;

    precompute_fused<<<1, 1024>>>(w2, w_sc, beta2, mean2, var2);
    resblock_main<<<TOTAL_ROWS / ROWS_PER_BLOCK, 256>>>(x, out);
}